// round 11
// baseline (speedup 1.0000x reference)
#include <cuda_runtime.h>
#include <cuda_fp16.h>
#include <cstdint>

#define BB 8
#define CC 128
#define NH 128
#define NW 128
#define C1 50
#define C2 18
#define HH 512
#define WW 512

// ---------------------------------------------------------------------------
// Device-global scratch
// ---------------------------------------------------------------------------
__device__ __align__(16) __half g_ctrlp[(size_t)BB * 8 * NH * NW * 16];
__device__ __align__(16) __half g_hp[(size_t)BB * 4 * NH * NW * 16];
__device__ float g_cond[(size_t)BB * C2 * NH * NW];
__device__ __align__(16) __half g_w1p[8 * 9 * 64 * 16];
__device__ __align__(16) __half g_w2p[4 * 9 * 32 * 16];

__device__ __forceinline__ uint32_t smem_u32(const void* p) {
    uint32_t a;
    asm("{ .reg .u64 t; cvta.to.shared.u64 t, %1; cvt.u32.u64 %0, t; }"
        : "=r"(a) : "l"(p));
    return a;
}

#define LDSM4(r, a)                                                            \
    asm volatile("ldmatrix.sync.aligned.m8n8.x4.shared.b16 {%0,%1,%2,%3}, [%4];" \
        : "=r"((r)[0]), "=r"((r)[1]), "=r"((r)[2]), "=r"((r)[3]) : "r"(a))

#define MMA16816(c, a, b0, b1)                                                 \
    asm volatile("mma.sync.aligned.m16n8k16.row.col.f32.f16.f16.f32 "          \
        "{%0,%1,%2,%3},{%4,%5,%6,%7},{%8,%9},{%0,%1,%2,%3};"                   \
        : "+f"((c)[0]), "+f"((c)[1]), "+f"((c)[2]), "+f"((c)[3])               \
        : "r"((a)[0]), "r"((a)[1]), "r"((a)[2]), "r"((a)[3]), "r"(b0), "r"(b1))

#define CPA16(dst, src, sz)                                                    \
    asm volatile("cp.async.cg.shared.global [%0], [%1], 16, %2;"               \
        :: "r"(dst), "l"(src), "r"(sz) : "memory")
#define CP_COMMIT() asm volatile("cp.async.commit_group;" ::: "memory")
#define CP_WAIT1()  asm volatile("cp.async.wait_group 1;" ::: "memory")
#define CP_WAIT0()  asm volatile("cp.async.wait_group 0;" ::: "memory")

__device__ __forceinline__ uint32_t pack_h2(__half a, __half b) {
    return (uint32_t)__half_as_ushort(a) | ((uint32_t)__half_as_ushort(b) << 16);
}

// ---------------------------------------------------------------------------
// prep_all: [0, 2048) ctrl conversion (4 y-rows per block); then weight packing
// ---------------------------------------------------------------------------
__global__ __launch_bounds__(256) void prep_all_kernel(
    const float* __restrict__ ctrl, const float* __restrict__ w1,
    const float* __restrict__ w2)
{
    __shared__ float sm[16 * 4 * 132];
    const int bid = blockIdx.x;
    const int tid = threadIdx.x;

    if (bid < 2048) {
        const int ys = bid & 31;
        const int bc = bid >> 5;
        const int chunk = bc & 7;
        const int b = bc >> 3;

        const float* src = ctrl + (((size_t)b * CC + chunk * 16) * NH + ys * 4) * NW;
#pragma unroll
        for (int it = 0; it < 8; it++) {
            int e = tid + it * 256;
            int r = e >> 5, xi = e & 31;
            int c = r >> 2, yl = r & 3;
            float4 v = *(const float4*)(src + (size_t)c * NH * NW + yl * NW + xi * 4);
            *(float4*)(sm + (c * 4 + yl) * 132 + xi * 4) = v;
        }
        __syncthreads();

#pragma unroll
        for (int it = 0; it < 4; it++) {
            int idx = tid + it * 256;
            int q = idx & 1, x = (idx >> 1) & 127, yl = idx >> 8;
            uint32_t u[4];
#pragma unroll
            for (int jp = 0; jp < 4; jp++) {
                int c0 = q * 8 + 2 * jp;
                __half o0 = __float2half(sm[(c0 * 4 + yl) * 132 + x]);
                __half o1 = __float2half(sm[((c0 + 1) * 4 + yl) * 132 + x]);
                u[jp] = pack_h2(o0, o1);
            }
            int y = ys * 4 + yl;
            float4* dst = ((float4*)g_ctrlp) +
                (((size_t)(bc * 128 + y) * 128 + x) * 2 + q);
            dst[0] = make_float4(__uint_as_float(u[0]), __uint_as_float(u[1]),
                                 __uint_as_float(u[2]), __uint_as_float(u[3]));
        }
    } else {
        int idx = (bid - 2048) * 256 + tid;
        if (idx < 8 * 9 * 64 * 16) {
            int jc = idx & 15;
            int oc = (idx >> 4) & 63;
            int r = idx >> 10;
            int tap = r % 9, chunk = r / 9;
            int dy = tap / 3, dx = tap % 3;
            float w = 0.f;
            if (oc < C1)
                w = w1[((oc * CC + chunk * 16 + jc) * 3 + dy) * 3 + dx];
            int q = (jc >> 3) ^ ((oc >> 2) & 1);
            g_w1p[((chunk * 9 + tap) * 64 + oc) * 16 + q * 8 + (jc & 7)] =
                __float2half(w);
        } else {
            int i2 = idx - 8 * 9 * 64 * 16;
            if (i2 < 4 * 9 * 32 * 16) {
                int jc = i2 & 15;
                int oc = (i2 >> 4) & 31;
                int r = i2 >> 9;
                int tap = r % 9, chunk = r / 9;
                int dy = tap / 3, dx = tap % 3;
                int cin = chunk * 16 + jc;
                float w = 0.f;
                if (oc < C2 && cin < C1)
                    w = w2[((oc * C1 + cin) * 3 + dy) * 3 + dx];
                int q = (jc >> 3) ^ ((oc >> 2) & 1);
                g_w2p[((chunk * 9 + tap) * 32 + oc) * 16 + q * 8 + (jc & 7)] =
                    __float2half(w);
            }
        }
    }
}

// ---------------------------------------------------------------------------
// conv1 mma (unchanged): M=256, N=64, K=8x9x16, double-buffered
// ---------------------------------------------------------------------------
#define C1_A_BUF 16640
#define C1_OFF_B 33280
#define C1_B_BUF 18432
#define C1_OFF_P 70144
#define C1_SMEM 70912

__global__ void __launch_bounds__(256, 2) conv1_mma_kernel(
    const float* __restrict__ b1, const float* __restrict__ gamma,
    const float* __restrict__ beta, const float* __restrict__ mean,
    const float* __restrict__ var)
{
    extern __shared__ char smem[];
    float* smemT = (float*)smem;
    float* smP = (float*)(smem + C1_OFF_P);
    const uint32_t sb = smem_u32(smem);
    const int tid = threadIdx.x;
    const int lane = tid & 31;
    const int warp = tid >> 5;
    const int b = blockIdx.x >> 6;
    const int y0 = (blockIdx.x & 63) * 2;
    const int wpx = (warp >> 1) * 64;
    const int wn = (warp & 1) * 32;

    if (tid < 64) {
        float s = 0.f, bb = 0.f, b1v = 0.f;
        if (tid < C1) {
            s = gamma[tid] * rsqrtf(var[tid] + 1e-5f);
            bb = beta[tid] - mean[tid] * s;
            b1v = b1[tid];
        }
        smP[tid] = b1v; smP[64 + tid] = s; smP[128 + tid] = bb;
    }
    if (tid < 32) {
        int q = tid & 1, col = (tid >> 1) & 1, s = (tid >> 2) & 3, d = (tid >> 4) & 1;
        int ri = s * 130 + (col ? 129 : 0);
        *(float4*)(smem + d * C1_A_BUF + ri * 32 + q * 16) =
            make_float4(0.f, 0.f, 0.f, 0.f);
    }

    const int rA = (lane & 7) + ((lane >> 3) & 1) * 8;
    const int qA = lane >> 4;
    int riA[4];
#pragma unroll
    for (int mt = 0; mt < 4; mt++) {
        int px = wpx + mt * 16 + rA;
        riA[mt] = (px >> 7) * 130 + (px & 127);
    }
    const int ocB = (lane & 7) + ((lane >> 4) << 3);
    const int qB = (lane >> 3) & 1;
    const int ocRow = wn + ocB;
    const uint32_t bSwz =
        sb + C1_OFF_B + (uint32_t)ocRow * 32 + (uint32_t)((qB ^ (ocRow >> 2)) & 1) * 16;

    float C[4][4][4];
#pragma unroll
    for (int i = 0; i < 4; i++)
#pragma unroll
        for (int j = 0; j < 4; j++)
#pragma unroll
            for (int k = 0; k < 4; k++) C[i][j][k] = 0.f;

    const char* ctrlBase = (const char*)g_ctrlp;
    const char* wBase = (const char*)g_w1p;

    auto stage = [&](int c, int d) {
        const char* srcA = ctrlBase + (size_t)(b * 8 + c) * (128 * 128 * 32);
        uint32_t aB = sb + d * C1_A_BUF;
#pragma unroll
        for (int it = 0; it < 4; it++) {
            int e = tid + it * 256;
            int s = e >> 8, r5 = e & 255;
            int x = r5 >> 1, q = r5 & 1;
            int gy = y0 - 1 + s;
            int gyc = gy < 0 ? 0 : (gy > 127 ? 127 : gy);
            const char* src = srcA + ((size_t)gyc * 128 + x) * 32 + q * 16;
            int ri = s * 130 + x + 1;
            uint32_t dst = aB + ri * 32 + ((q ^ (ri >> 2)) & 1) * 16;
            CPA16(dst, src, ((unsigned)gy < 128u) ? 16 : 0);
        }
        uint32_t bBf = sb + C1_OFF_B + d * C1_B_BUF;
        const char* srcB = wBase + (size_t)c * C1_B_BUF;
        for (int e = tid; e < 1152; e += 256)
            CPA16(bBf + e * 16, srcB + e * 16, 16);
        CP_COMMIT();
    };

    stage(0, 0);
    for (int c = 0; c < 8; c++) {
        if (c < 7) { stage(c + 1, (c + 1) & 1); CP_WAIT1(); }
        else CP_WAIT0();
        __syncthreads();

        const uint32_t aBuf = sb + (c & 1) * C1_A_BUF;
        const uint32_t bBuf = bSwz + (c & 1) * C1_B_BUF;
#pragma unroll
        for (int dy = 0; dy < 3; dy++) {
#pragma unroll
            for (int dx = 0; dx < 3; dx++) {
                const int tap = dy * 3 + dx;
                uint32_t bh[8];
                uint32_t bt = bBuf + tap * 2048;
                LDSM4(bh, bt);
                LDSM4(bh + 4, bt + 512);
                uint32_t a[16];
#pragma unroll
                for (int mt = 0; mt < 4; mt++) {
                    int rt = riA[mt] + dy * 130 + dx;
                    uint32_t ad = aBuf + rt * 32 + ((qA ^ (rt >> 2)) & 1) * 16;
                    LDSM4(a + mt * 4, ad);
                }
#pragma unroll
                for (int mt = 0; mt < 4; mt++)
#pragma unroll
                    for (int nt = 0; nt < 4; nt++)
                        MMA16816(C[mt][nt], a + mt * 4, bh[nt * 2], bh[nt * 2 + 1]);
            }
        }
        __syncthreads();
    }

    {
        const int g2 = lane >> 2, t4 = lane & 3;
#pragma unroll
        for (int mt = 0; mt < 4; mt++) {
#pragma unroll
            for (int nt = 0; nt < 4; nt++) {
                int px = wpx + mt * 16 + g2;
                int oc = wn + nt * 8 + t4 * 2;
                smemT[oc * 265 + px] = C[mt][nt][0];
                smemT[(oc + 1) * 265 + px] = C[mt][nt][1];
                smemT[oc * 265 + px + 8] = C[mt][nt][2];
                smemT[(oc + 1) * 265 + px + 8] = C[mt][nt][3];
            }
        }
    }
    __syncthreads();
    for (int e = tid; e < 1024; e += 256) {
        int c = e >> 8, px = e & 255;
        int gy = y0 + (px >> 7), x = px & 127;
        uint32_t uh[8];
#pragma unroll
        for (int jp = 0; jp < 8; jp++) {
            __half oh[2];
#pragma unroll
            for (int t = 0; t < 2; t++) {
                int oc = c * 16 + 2 * jp + t;
                float val = 0.f;
                if (oc < C1) {
                    float acc = smemT[oc * 265 + px];
                    val = fmaxf(acc + smP[oc], 0.f) * smP[64 + oc] + smP[128 + oc];
                }
                oh[t] = __float2half(val);
            }
            uh[jp] = pack_h2(oh[0], oh[1]);
        }
        float4* dst = ((float4*)g_hp) + (((size_t)(b * 4 + c) * 128 + gy) * 128 + x) * 2;
        dst[0] = make_float4(__uint_as_float(uh[0]), __uint_as_float(uh[1]),
                             __uint_as_float(uh[2]), __uint_as_float(uh[3]));
        dst[1] = make_float4(__uint_as_float(uh[4]), __uint_as_float(uh[5]),
                             __uint_as_float(uh[6]), __uint_as_float(uh[7]));
    }
}

// ---------------------------------------------------------------------------
// conv2 mma (unchanged): M=512, N=32 (18 used), K=4x9x16. grid=256.
// ---------------------------------------------------------------------------
#define C2_A_BUF 24960
#define C2_OFF_B 49920
#define C2_B_BUF 9216
#define C2_SMEM 68352

__global__ void __launch_bounds__(256, 2) conv2_mma_kernel(const float* __restrict__ b2)
{
    extern __shared__ char smem[];
    float* smemT = (float*)smem;
    const uint32_t sb = smem_u32(smem);
    const int tid = threadIdx.x;
    const int lane = tid & 31;
    const int warp = tid >> 5;
    const int b = blockIdx.x >> 5;
    const int y0 = (blockIdx.x & 31) * 4;
    const int wpx = warp * 64;

    if (tid < 48) {
        int q = tid & 1, col = (tid >> 1) & 1, s = (tid >> 2) % 6, d = tid >= 24 ? 1 : 0;
        int ri = s * 130 + (col ? 129 : 0);
        *(float4*)(smem + d * C2_A_BUF + ri * 32 + q * 16) =
            make_float4(0.f, 0.f, 0.f, 0.f);
    }

    const int rA = (lane & 7) + ((lane >> 3) & 1) * 8;
    const int qA = lane >> 4;
    int riA[4];
#pragma unroll
    for (int mt = 0; mt < 4; mt++) {
        int px = wpx + mt * 16 + rA;
        riA[mt] = (px >> 7) * 130 + (px & 127);
    }
    const int ocB = (lane & 7) + ((lane >> 4) << 3);
    const int qB = (lane >> 3) & 1;
    const uint32_t bSwz =
        sb + C2_OFF_B + (uint32_t)ocB * 32 + (uint32_t)((qB ^ (ocB >> 2)) & 1) * 16;

    float C[4][4][4];
#pragma unroll
    for (int i = 0; i < 4; i++)
#pragma unroll
        for (int j = 0; j < 4; j++)
#pragma unroll
            for (int k = 0; k < 4; k++) C[i][j][k] = 0.f;

    const char* hpBase = (const char*)g_hp;
    const char* wBase = (const char*)g_w2p;

    auto stage = [&](int c, int d) {
        const char* srcA = hpBase + (size_t)(b * 4 + c) * (128 * 128 * 32);
        uint32_t aB = sb + d * C2_A_BUF;
#pragma unroll
        for (int it = 0; it < 6; it++) {
            int e = tid + it * 256;
            int s = e >> 8, r5 = e & 255;
            int x = r5 >> 1, q = r5 & 1;
            int gy = y0 - 1 + s;
            int gyc = gy < 0 ? 0 : (gy > 127 ? 127 : gy);
            const char* src = srcA + ((size_t)gyc * 128 + x) * 32 + q * 16;
            int ri = s * 130 + x + 1;
            uint32_t dst = aB + ri * 32 + ((q ^ (ri >> 2)) & 1) * 16;
            CPA16(dst, src, ((unsigned)gy < 128u) ? 16 : 0);
        }
        uint32_t bBf = sb + C2_OFF_B + d * C2_B_BUF;
        const char* srcB = wBase + (size_t)c * C2_B_BUF;
        for (int e = tid; e < 576; e += 256)
            CPA16(bBf + e * 16, srcB + e * 16, 16);
        CP_COMMIT();
    };

    stage(0, 0);
    for (int c = 0; c < 4; c++) {
        if (c < 3) { stage(c + 1, (c + 1) & 1); CP_WAIT1(); }
        else CP_WAIT0();
        __syncthreads();

        const uint32_t aBuf = sb + (c & 1) * C2_A_BUF;
        const uint32_t bBuf = bSwz + (c & 1) * C2_B_BUF;
#pragma unroll
        for (int dy = 0; dy < 3; dy++) {
#pragma unroll
            for (int dx = 0; dx < 3; dx++) {
                const int tap = dy * 3 + dx;
                uint32_t bh[8];
                uint32_t bt = bBuf + tap * 1024;
                LDSM4(bh, bt);
                LDSM4(bh + 4, bt + 512);
                uint32_t a[16];
#pragma unroll
                for (int mt = 0; mt < 4; mt++) {
                    int rt = riA[mt] + dy * 130 + dx;
                    uint32_t ad = aBuf + rt * 32 + ((qA ^ (rt >> 2)) & 1) * 16;
                    LDSM4(a + mt * 4, ad);
                }
#pragma unroll
                for (int mt = 0; mt < 4; mt++)
#pragma unroll
                    for (int nt = 0; nt < 4; nt++)
                        MMA16816(C[mt][nt], a + mt * 4, bh[nt * 2], bh[nt * 2 + 1]);
            }
        }
        __syncthreads();
    }

    {
        const int g2 = lane >> 2, t4 = lane & 3;
#pragma unroll
        for (int mt = 0; mt < 4; mt++) {
#pragma unroll
            for (int nt = 0; nt < 4; nt++) {
                int px = wpx + mt * 16 + g2;
                int oc = nt * 8 + t4 * 2;
                smemT[oc * 516 + px] = C[mt][nt][0];
                smemT[(oc + 1) * 516 + px] = C[mt][nt][1];
                smemT[oc * 516 + px + 8] = C[mt][nt][2];
                smemT[(oc + 1) * 516 + px + 8] = C[mt][nt][3];
            }
        }
    }
    __syncthreads();
    for (int e = tid; e < C2 * 128; e += 256) {
        int oc = e >> 7, pq = e & 127;
        int px0 = pq * 4;
        int gy = y0 + (px0 >> 7), x = px0 & 127;
        float bv = b2[oc];
        float4 v = *(float4*)(smemT + oc * 516 + px0);
        v.x += bv; v.y += bv; v.z += bv; v.w += bv;
        *(float4*)(g_cond + (((size_t)b * C2 + oc) * NH + gy) * NW + x) = v;
    }
}

// ---------------------------------------------------------------------------
// translate: smem row-cache. Block (128,2) = cellY pair x ch x b.
// Stages the 16 distinct image rows (float4) once, taps via LDS.
// ---------------------------------------------------------------------------
__global__ __launch_bounds__(256) void translate_kernel(
    const float* __restrict__ image, float* __restrict__ out)
{
    __shared__ float4 sIm[16][128];
    const int tx = threadIdx.x;               // 0..127 = cell x = float4 col
    const int ty = threadIdx.y;               // 0..1
    const int tid = ty * 128 + tx;
    const int cy0 = blockIdx.x * 2;
    const int ch = blockIdx.y;
    const int b = blockIdx.z;
    const int g = ch / 3;

    const float4* img4 = (const float4*)image + (size_t)(b * 6 + ch) * HH * (WW / 4);

    // stage rows 4*cy0-4 .. 4*cy0+11 (zero-fill OOB)
#pragma unroll
    for (int it = 0; it < 8; it++) {
        int e = tid + it * 256;
        int rr = e >> 7, x = e & 127;
        int gy = cy0 * 4 - 4 + rr;
        float4 v = make_float4(0.f, 0.f, 0.f, 0.f);
        if ((unsigned)gy < (unsigned)HH) v = img4[(size_t)gy * (WW / 4) + x];
        sIm[rr][x] = v;
    }

    const int cellY = cy0 + ty;
    float wk[9];
    const float* cond_b = g_cond + ((size_t)b * C2 + g * 9) * NH * NW;
#pragma unroll
    for (int k = 0; k < 9; k++)
        wk[k] = cond_b[(size_t)k * NH * NW + (size_t)cellY * NW + tx];
    __syncthreads();

    float4* out4 = (float4*)out + (size_t)(b * 6 + ch) * HH * (WW / 4);

#pragma unroll
    for (int r = 0; r < 4; r++) {
        float4 acc = make_float4(0.f, 0.f, 0.f, 0.f);
#pragma unroll
        for (int i = 0; i < 3; i++) {
            int xf = tx - 1 + i;
            if ((unsigned)xf >= (unsigned)(WW / 4)) continue;
#pragma unroll
            for (int j = 0; j < 3; j++) {
                int lr = 4 * ty + r + 4 * j;   // local row: tap y - (4*cy0-4)
                float w = wk[i * 3 + j];
                float4 v = sIm[lr][xf];
                acc.x += v.x * w; acc.y += v.y * w;
                acc.z += v.z * w; acc.w += v.w * w;
            }
        }
        out4[(size_t)(cellY * 4 + r) * (WW / 4) + tx] = acc;
    }
}

// ---------------------------------------------------------------------------
extern "C" void kernel_launch(void* const* d_in, const int* in_sizes, int n_in,
                              void* d_out, int out_size)
{
    const float* image = (const float*)d_in[0];
    const float* ctrl  = (const float*)d_in[1];
    const float* w1    = (const float*)d_in[2];
    const float* b1    = (const float*)d_in[3];
    const float* gamma = (const float*)d_in[4];
    const float* beta  = (const float*)d_in[5];
    const float* mean  = (const float*)d_in[6];
    const float* var   = (const float*)d_in[7];
    const float* w2    = (const float*)d_in[8];
    const float* b2    = (const float*)d_in[9];
    float* out = (float*)d_out;

    static int smem_set = 0;
    if (!smem_set) {
        cudaFuncSetAttribute(conv1_mma_kernel,
                             cudaFuncAttributeMaxDynamicSharedMemorySize, C1_SMEM);
        cudaFuncSetAttribute(conv2_mma_kernel,
                             cudaFuncAttributeMaxDynamicSharedMemorySize, C2_SMEM);
        smem_set = 1;
    }

    prep_all_kernel<<<2048 + 360, 256>>>(ctrl, w1, w2);
    conv1_mma_kernel<<<BB * 64, 256, C1_SMEM>>>(b1, gamma, beta, mean, var);
    conv2_mma_kernel<<<BB * 32, 256, C2_SMEM>>>(b2);
    translate_kernel<<<dim3(64, 6, BB), dim3(128, 2)>>>(image, out);
}

// round 12
// speedup vs baseline: 1.0271x; 1.0271x over previous
#include <cuda_runtime.h>
#include <cuda_fp16.h>
#include <cstdint>

#define BB 8
#define CC 128
#define NH 128
#define NW 128
#define C1 50
#define C2 18
#define HH 512
#define WW 512

// ---------------------------------------------------------------------------
// Device-global scratch
// ---------------------------------------------------------------------------
__device__ __align__(16) __half g_ctrlp[(size_t)BB * 8 * NH * NW * 16];
__device__ __align__(16) __half g_hp[(size_t)BB * 4 * NH * NW * 16];
__device__ float g_cond[(size_t)BB * C2 * NH * NW];
__device__ __align__(16) __half g_w1p[8 * 9 * 64 * 16];
__device__ __align__(16) __half g_w2p[4 * 9 * 32 * 16];

__device__ __forceinline__ uint32_t smem_u32(const void* p) {
    uint32_t a;
    asm("{ .reg .u64 t; cvta.to.shared.u64 t, %1; cvt.u32.u64 %0, t; }"
        : "=r"(a) : "l"(p));
    return a;
}

#define LDSM4(r, a)                                                            \
    asm volatile("ldmatrix.sync.aligned.m8n8.x4.shared.b16 {%0,%1,%2,%3}, [%4];" \
        : "=r"((r)[0]), "=r"((r)[1]), "=r"((r)[2]), "=r"((r)[3]) : "r"(a))

#define MMA16816(c, a, b0, b1)                                                 \
    asm volatile("mma.sync.aligned.m16n8k16.row.col.f32.f16.f16.f32 "          \
        "{%0,%1,%2,%3},{%4,%5,%6,%7},{%8,%9},{%0,%1,%2,%3};"                   \
        : "+f"((c)[0]), "+f"((c)[1]), "+f"((c)[2]), "+f"((c)[3])               \
        : "r"((a)[0]), "r"((a)[1]), "r"((a)[2]), "r"((a)[3]), "r"(b0), "r"(b1))

#define CPA16(dst, src, sz)                                                    \
    asm volatile("cp.async.cg.shared.global [%0], [%1], 16, %2;"               \
        :: "r"(dst), "l"(src), "r"(sz) : "memory")
#define CP_COMMIT() asm volatile("cp.async.commit_group;" ::: "memory")
#define CP_WAIT1()  asm volatile("cp.async.wait_group 1;" ::: "memory")
#define CP_WAIT0()  asm volatile("cp.async.wait_group 0;" ::: "memory")

__device__ __forceinline__ uint32_t pack_h2(__half a, __half b) {
    return (uint32_t)__half_as_ushort(a) | ((uint32_t)__half_as_ushort(b) << 16);
}

// ---------------------------------------------------------------------------
// prep_all: [0, 2048) ctrl conversion (4 y-rows per block); then weight packing
// ---------------------------------------------------------------------------
__global__ __launch_bounds__(256) void prep_all_kernel(
    const float* __restrict__ ctrl, const float* __restrict__ w1,
    const float* __restrict__ w2)
{
    __shared__ float sm[16 * 4 * 132];
    const int bid = blockIdx.x;
    const int tid = threadIdx.x;

    if (bid < 2048) {
        const int ys = bid & 31;
        const int bc = bid >> 5;
        const int chunk = bc & 7;
        const int b = bc >> 3;

        const float* src = ctrl + (((size_t)b * CC + chunk * 16) * NH + ys * 4) * NW;
#pragma unroll
        for (int it = 0; it < 8; it++) {
            int e = tid + it * 256;
            int r = e >> 5, xi = e & 31;
            int c = r >> 2, yl = r & 3;
            float4 v = *(const float4*)(src + (size_t)c * NH * NW + yl * NW + xi * 4);
            *(float4*)(sm + (c * 4 + yl) * 132 + xi * 4) = v;
        }
        __syncthreads();

#pragma unroll
        for (int it = 0; it < 4; it++) {
            int idx = tid + it * 256;
            int q = idx & 1, x = (idx >> 1) & 127, yl = idx >> 8;
            uint32_t u[4];
#pragma unroll
            for (int jp = 0; jp < 4; jp++) {
                int c0 = q * 8 + 2 * jp;
                __half o0 = __float2half(sm[(c0 * 4 + yl) * 132 + x]);
                __half o1 = __float2half(sm[((c0 + 1) * 4 + yl) * 132 + x]);
                u[jp] = pack_h2(o0, o1);
            }
            int y = ys * 4 + yl;
            float4* dst = ((float4*)g_ctrlp) +
                (((size_t)(bc * 128 + y) * 128 + x) * 2 + q);
            dst[0] = make_float4(__uint_as_float(u[0]), __uint_as_float(u[1]),
                                 __uint_as_float(u[2]), __uint_as_float(u[3]));
        }
    } else {
        int idx = (bid - 2048) * 256 + tid;
        if (idx < 8 * 9 * 64 * 16) {
            int jc = idx & 15;
            int oc = (idx >> 4) & 63;
            int r = idx >> 10;
            int tap = r % 9, chunk = r / 9;
            int dy = tap / 3, dx = tap % 3;
            float w = 0.f;
            if (oc < C1)
                w = w1[((oc * CC + chunk * 16 + jc) * 3 + dy) * 3 + dx];
            int q = (jc >> 3) ^ ((oc >> 2) & 1);
            g_w1p[((chunk * 9 + tap) * 64 + oc) * 16 + q * 8 + (jc & 7)] =
                __float2half(w);
        } else {
            int i2 = idx - 8 * 9 * 64 * 16;
            if (i2 < 4 * 9 * 32 * 16) {
                int jc = i2 & 15;
                int oc = (i2 >> 4) & 31;
                int r = i2 >> 9;
                int tap = r % 9, chunk = r / 9;
                int dy = tap / 3, dx = tap % 3;
                int cin = chunk * 16 + jc;
                float w = 0.f;
                if (oc < C2 && cin < C1)
                    w = w2[((oc * C1 + cin) * 3 + dy) * 3 + dx];
                int q = (jc >> 3) ^ ((oc >> 2) & 1);
                g_w2p[((chunk * 9 + tap) * 32 + oc) * 16 + q * 8 + (jc & 7)] =
                    __float2half(w);
            }
        }
    }
}

// ---------------------------------------------------------------------------
// conv1 mma: M=256, N=64, K=8x9x16, cp.async double-buffered
// ---------------------------------------------------------------------------
#define C1_A_BUF 16640
#define C1_OFF_B 33280
#define C1_B_BUF 18432
#define C1_OFF_P 70144
#define C1_SMEM 70912

__global__ void __launch_bounds__(256, 2) conv1_mma_kernel(
    const float* __restrict__ b1, const float* __restrict__ gamma,
    const float* __restrict__ beta, const float* __restrict__ mean,
    const float* __restrict__ var)
{
    extern __shared__ char smem[];
    float* smemT = (float*)smem;
    float* smP = (float*)(smem + C1_OFF_P);
    const uint32_t sb = smem_u32(smem);
    const int tid = threadIdx.x;
    const int lane = tid & 31;
    const int warp = tid >> 5;
    const int b = blockIdx.x >> 6;
    const int y0 = (blockIdx.x & 63) * 2;
    const int wpx = (warp >> 1) * 64;
    const int wn = (warp & 1) * 32;

    if (tid < 64) {
        float s = 0.f, bb = 0.f, b1v = 0.f;
        if (tid < C1) {
            s = gamma[tid] * rsqrtf(var[tid] + 1e-5f);
            bb = beta[tid] - mean[tid] * s;
            b1v = b1[tid];
        }
        smP[tid] = b1v; smP[64 + tid] = s; smP[128 + tid] = bb;
    }
    if (tid < 32) {
        int q = tid & 1, col = (tid >> 1) & 1, s = (tid >> 2) & 3, d = (tid >> 4) & 1;
        int ri = s * 130 + (col ? 129 : 0);
        *(float4*)(smem + d * C1_A_BUF + ri * 32 + q * 16) =
            make_float4(0.f, 0.f, 0.f, 0.f);
    }

    const int rA = (lane & 7) + ((lane >> 3) & 1) * 8;
    const int qA = lane >> 4;
    int riA[4];
#pragma unroll
    for (int mt = 0; mt < 4; mt++) {
        int px = wpx + mt * 16 + rA;
        riA[mt] = (px >> 7) * 130 + (px & 127);
    }
    const int ocB = (lane & 7) + ((lane >> 4) << 3);
    const int qB = (lane >> 3) & 1;
    const int ocRow = wn + ocB;
    const uint32_t bSwz =
        sb + C1_OFF_B + (uint32_t)ocRow * 32 + (uint32_t)((qB ^ (ocRow >> 2)) & 1) * 16;

    float C[4][4][4];
#pragma unroll
    for (int i = 0; i < 4; i++)
#pragma unroll
        for (int j = 0; j < 4; j++)
#pragma unroll
            for (int k = 0; k < 4; k++) C[i][j][k] = 0.f;

    const char* ctrlBase = (const char*)g_ctrlp;
    const char* wBase = (const char*)g_w1p;

    auto stage = [&](int c, int d) {
        const char* srcA = ctrlBase + (size_t)(b * 8 + c) * (128 * 128 * 32);
        uint32_t aB = sb + d * C1_A_BUF;
#pragma unroll
        for (int it = 0; it < 4; it++) {
            int e = tid + it * 256;
            int s = e >> 8, r5 = e & 255;
            int x = r5 >> 1, q = r5 & 1;
            int gy = y0 - 1 + s;
            int gyc = gy < 0 ? 0 : (gy > 127 ? 127 : gy);
            const char* src = srcA + ((size_t)gyc * 128 + x) * 32 + q * 16;
            int ri = s * 130 + x + 1;
            uint32_t dst = aB + ri * 32 + ((q ^ (ri >> 2)) & 1) * 16;
            CPA16(dst, src, ((unsigned)gy < 128u) ? 16 : 0);
        }
        uint32_t bBf = sb + C1_OFF_B + d * C1_B_BUF;
        const char* srcB = wBase + (size_t)c * C1_B_BUF;
        for (int e = tid; e < 1152; e += 256)
            CPA16(bBf + e * 16, srcB + e * 16, 16);
        CP_COMMIT();
    };

    stage(0, 0);
    for (int c = 0; c < 8; c++) {
        if (c < 7) { stage(c + 1, (c + 1) & 1); CP_WAIT1(); }
        else CP_WAIT0();
        __syncthreads();

        const uint32_t aBuf = sb + (c & 1) * C1_A_BUF;
        const uint32_t bBuf = bSwz + (c & 1) * C1_B_BUF;
#pragma unroll
        for (int dy = 0; dy < 3; dy++) {
#pragma unroll
            for (int dx = 0; dx < 3; dx++) {
                const int tap = dy * 3 + dx;
                uint32_t bh[8];
                uint32_t bt = bBuf + tap * 2048;
                LDSM4(bh, bt);
                LDSM4(bh + 4, bt + 512);
                uint32_t a[16];
#pragma unroll
                for (int mt = 0; mt < 4; mt++) {
                    int rt = riA[mt] + dy * 130 + dx;
                    uint32_t ad = aBuf + rt * 32 + ((qA ^ (rt >> 2)) & 1) * 16;
                    LDSM4(a + mt * 4, ad);
                }
#pragma unroll
                for (int mt = 0; mt < 4; mt++)
#pragma unroll
                    for (int nt = 0; nt < 4; nt++)
                        MMA16816(C[mt][nt], a + mt * 4, bh[nt * 2], bh[nt * 2 + 1]);
            }
        }
        __syncthreads();
    }

    {
        const int g2 = lane >> 2, t4 = lane & 3;
#pragma unroll
        for (int mt = 0; mt < 4; mt++) {
#pragma unroll
            for (int nt = 0; nt < 4; nt++) {
                int px = wpx + mt * 16 + g2;
                int oc = wn + nt * 8 + t4 * 2;
                smemT[oc * 265 + px] = C[mt][nt][0];
                smemT[(oc + 1) * 265 + px] = C[mt][nt][1];
                smemT[oc * 265 + px + 8] = C[mt][nt][2];
                smemT[(oc + 1) * 265 + px + 8] = C[mt][nt][3];
            }
        }
    }
    __syncthreads();
    for (int e = tid; e < 1024; e += 256) {
        int c = e >> 8, px = e & 255;
        int gy = y0 + (px >> 7), x = px & 127;
        uint32_t uh[8];
#pragma unroll
        for (int jp = 0; jp < 8; jp++) {
            __half oh[2];
#pragma unroll
            for (int t = 0; t < 2; t++) {
                int oc = c * 16 + 2 * jp + t;
                float val = 0.f;
                if (oc < C1) {
                    float acc = smemT[oc * 265 + px];
                    val = fmaxf(acc + smP[oc], 0.f) * smP[64 + oc] + smP[128 + oc];
                }
                oh[t] = __float2half(val);
            }
            uh[jp] = pack_h2(oh[0], oh[1]);
        }
        float4* dst = ((float4*)g_hp) + (((size_t)(b * 4 + c) * 128 + gy) * 128 + x) * 2;
        dst[0] = make_float4(__uint_as_float(uh[0]), __uint_as_float(uh[1]),
                             __uint_as_float(uh[2]), __uint_as_float(uh[3]));
        dst[1] = make_float4(__uint_as_float(uh[4]), __uint_as_float(uh[5]),
                             __uint_as_float(uh[6]), __uint_as_float(uh[7]));
    }
}

// ---------------------------------------------------------------------------
// conv2 mma: M=512, N=32 (18 used), K=4x9x16. grid=256.
// ---------------------------------------------------------------------------
#define C2_A_BUF 24960
#define C2_OFF_B 49920
#define C2_B_BUF 9216
#define C2_SMEM 68352

__global__ void __launch_bounds__(256, 2) conv2_mma_kernel(const float* __restrict__ b2)
{
    extern __shared__ char smem[];
    float* smemT = (float*)smem;
    const uint32_t sb = smem_u32(smem);
    const int tid = threadIdx.x;
    const int lane = tid & 31;
    const int warp = tid >> 5;
    const int b = blockIdx.x >> 5;
    const int y0 = (blockIdx.x & 31) * 4;
    const int wpx = warp * 64;

    if (tid < 48) {
        int q = tid & 1, col = (tid >> 1) & 1, s = (tid >> 2) % 6, d = tid >= 24 ? 1 : 0;
        int ri = s * 130 + (col ? 129 : 0);
        *(float4*)(smem + d * C2_A_BUF + ri * 32 + q * 16) =
            make_float4(0.f, 0.f, 0.f, 0.f);
    }

    const int rA = (lane & 7) + ((lane >> 3) & 1) * 8;
    const int qA = lane >> 4;
    int riA[4];
#pragma unroll
    for (int mt = 0; mt < 4; mt++) {
        int px = wpx + mt * 16 + rA;
        riA[mt] = (px >> 7) * 130 + (px & 127);
    }
    const int ocB = (lane & 7) + ((lane >> 4) << 3);
    const int qB = (lane >> 3) & 1;
    const uint32_t bSwz =
        sb + C2_OFF_B + (uint32_t)ocB * 32 + (uint32_t)((qB ^ (ocB >> 2)) & 1) * 16;

    float C[4][4][4];
#pragma unroll
    for (int i = 0; i < 4; i++)
#pragma unroll
        for (int j = 0; j < 4; j++)
#pragma unroll
            for (int k = 0; k < 4; k++) C[i][j][k] = 0.f;

    const char* hpBase = (const char*)g_hp;
    const char* wBase = (const char*)g_w2p;

    auto stage = [&](int c, int d) {
        const char* srcA = hpBase + (size_t)(b * 4 + c) * (128 * 128 * 32);
        uint32_t aB = sb + d * C2_A_BUF;
#pragma unroll
        for (int it = 0; it < 6; it++) {
            int e = tid + it * 256;
            int s = e >> 8, r5 = e & 255;
            int x = r5 >> 1, q = r5 & 1;
            int gy = y0 - 1 + s;
            int gyc = gy < 0 ? 0 : (gy > 127 ? 127 : gy);
            const char* src = srcA + ((size_t)gyc * 128 + x) * 32 + q * 16;
            int ri = s * 130 + x + 1;
            uint32_t dst = aB + ri * 32 + ((q ^ (ri >> 2)) & 1) * 16;
            CPA16(dst, src, ((unsigned)gy < 128u) ? 16 : 0);
        }
        uint32_t bBf = sb + C2_OFF_B + d * C2_B_BUF;
        const char* srcB = wBase + (size_t)c * C2_B_BUF;
        for (int e = tid; e < 576; e += 256)
            CPA16(bBf + e * 16, srcB + e * 16, 16);
        CP_COMMIT();
    };

    stage(0, 0);
    for (int c = 0; c < 4; c++) {
        if (c < 3) { stage(c + 1, (c + 1) & 1); CP_WAIT1(); }
        else CP_WAIT0();
        __syncthreads();

        const uint32_t aBuf = sb + (c & 1) * C2_A_BUF;
        const uint32_t bBuf = bSwz + (c & 1) * C2_B_BUF;
#pragma unroll
        for (int dy = 0; dy < 3; dy++) {
#pragma unroll
            for (int dx = 0; dx < 3; dx++) {
                const int tap = dy * 3 + dx;
                uint32_t bh[8];
                uint32_t bt = bBuf + tap * 1024;
                LDSM4(bh, bt);
                LDSM4(bh + 4, bt + 512);
                uint32_t a[16];
#pragma unroll
                for (int mt = 0; mt < 4; mt++) {
                    int rt = riA[mt] + dy * 130 + dx;
                    uint32_t ad = aBuf + rt * 32 + ((qA ^ (rt >> 2)) & 1) * 16;
                    LDSM4(a + mt * 4, ad);
                }
#pragma unroll
                for (int mt = 0; mt < 4; mt++)
#pragma unroll
                    for (int nt = 0; nt < 4; nt++)
                        MMA16816(C[mt][nt], a + mt * 4, bh[nt * 2], bh[nt * 2 + 1]);
            }
        }
        __syncthreads();
    }

    {
        const int g2 = lane >> 2, t4 = lane & 3;
#pragma unroll
        for (int mt = 0; mt < 4; mt++) {
#pragma unroll
            for (int nt = 0; nt < 4; nt++) {
                int px = wpx + mt * 16 + g2;
                int oc = nt * 8 + t4 * 2;
                smemT[oc * 516 + px] = C[mt][nt][0];
                smemT[(oc + 1) * 516 + px] = C[mt][nt][1];
                smemT[oc * 516 + px + 8] = C[mt][nt][2];
                smemT[(oc + 1) * 516 + px + 8] = C[mt][nt][3];
            }
        }
    }
    __syncthreads();
    for (int e = tid; e < C2 * 128; e += 256) {
        int oc = e >> 7, pq = e & 127;
        int px0 = pq * 4;
        int gy = y0 + (px0 >> 7), x = px0 & 127;
        float bv = b2[oc];
        float4 v = *(float4*)(smemT + oc * 516 + px0);
        v.x += bv; v.y += bv; v.z += bv; v.w += bv;
        *(float4*)(g_cond + (((size_t)b * C2 + oc) * NH + gy) * NW + x) = v;
    }
}

// ---------------------------------------------------------------------------
// translate — R10/R4 exact version (1 cell/thread; measured 26.2us best)
// ---------------------------------------------------------------------------
__global__ __launch_bounds__(256) void translate_kernel(
    const float* __restrict__ image, float* __restrict__ out)
{
    const int x4 = threadIdx.x;
    const int cellY = blockIdx.x * 2 + threadIdx.y;
    const int ch = blockIdx.y;
    const int b = blockIdx.z;
    const int g = ch / 3;

    float wk[9];
    const float* cond_b = g_cond + ((size_t)b * C2 + g * 9) * NH * NW;
#pragma unroll
    for (int k = 0; k < 9; k++)
        wk[k] = cond_b[(size_t)k * NH * NW + (size_t)cellY * NW + x4];

    const float4* img4 = (const float4*)image + (size_t)(b * 6 + ch) * HH * (WW / 4);
    float4* out4 = (float4*)out + (size_t)(b * 6 + ch) * HH * (WW / 4);

#pragma unroll
    for (int r = 0; r < 4; r++) {
        int y = cellY * 4 + r;
        float4 acc = make_float4(0.f, 0.f, 0.f, 0.f);
#pragma unroll
        for (int i = 0; i < 3; i++) {
            int xf = x4 + i - 1;
            if ((unsigned)xf >= (unsigned)(WW / 4)) continue;
#pragma unroll
            for (int j = 0; j < 3; j++) {
                int yy = y + j * 4 - 4;
                if ((unsigned)yy >= (unsigned)HH) continue;
                float w = wk[i * 3 + j];
                float4 v = img4[(size_t)yy * (WW / 4) + xf];
                acc.x += v.x * w; acc.y += v.y * w;
                acc.z += v.z * w; acc.w += v.w * w;
            }
        }
        out4[(size_t)y * (WW / 4) + x4] = acc;
    }
}

// ---------------------------------------------------------------------------
extern "C" void kernel_launch(void* const* d_in, const int* in_sizes, int n_in,
                              void* d_out, int out_size)
{
    const float* image = (const float*)d_in[0];
    const float* ctrl  = (const float*)d_in[1];
    const float* w1    = (const float*)d_in[2];
    const float* b1    = (const float*)d_in[3];
    const float* gamma = (const float*)d_in[4];
    const float* beta  = (const float*)d_in[5];
    const float* mean  = (const float*)d_in[6];
    const float* var   = (const float*)d_in[7];
    const float* w2    = (const float*)d_in[8];
    const float* b2    = (const float*)d_in[9];
    float* out = (float*)d_out;

    static int smem_set = 0;
    if (!smem_set) {
        cudaFuncSetAttribute(conv1_mma_kernel,
                             cudaFuncAttributeMaxDynamicSharedMemorySize, C1_SMEM);
        cudaFuncSetAttribute(conv2_mma_kernel,
                             cudaFuncAttributeMaxDynamicSharedMemorySize, C2_SMEM);
        smem_set = 1;
    }

    prep_all_kernel<<<2048 + 360, 256>>>(ctrl, w1, w2);
    conv1_mma_kernel<<<BB * 64, 256, C1_SMEM>>>(b1, gamma, beta, mean, var);
    conv2_mma_kernel<<<BB * 32, 256, C2_SMEM>>>(b2);
    translate_kernel<<<dim3(64, 6, BB), dim3(128, 2)>>>(image, out);
}

// round 13
// speedup vs baseline: 1.0289x; 1.0018x over previous
#include <cuda_runtime.h>
#include <cuda_fp16.h>
#include <cstdint>

#define BB 8
#define CC 128
#define NH 128
#define NW 128
#define C1 50
#define C2 18
#define HH 512
#define WW 512

// ---------------------------------------------------------------------------
// Device-global scratch
// ---------------------------------------------------------------------------
__device__ __align__(16) __half g_ctrlp[(size_t)BB * 8 * NH * NW * 16];
__device__ __align__(16) __half g_hp[(size_t)BB * 4 * NH * NW * 16];
__device__ float g_cond[(size_t)BB * C2 * NH * NW];
__device__ __align__(16) __half g_w1p[8 * 9 * 64 * 16];
__device__ __align__(16) __half g_w2p[4 * 9 * 32 * 16];

__device__ __forceinline__ uint32_t smem_u32(const void* p) {
    uint32_t a;
    asm("{ .reg .u64 t; cvta.to.shared.u64 t, %1; cvt.u32.u64 %0, t; }"
        : "=r"(a) : "l"(p));
    return a;
}

#define LDSM4(r, a)                                                            \
    asm volatile("ldmatrix.sync.aligned.m8n8.x4.shared.b16 {%0,%1,%2,%3}, [%4];" \
        : "=r"((r)[0]), "=r"((r)[1]), "=r"((r)[2]), "=r"((r)[3]) : "r"(a))

#define MMA16816(c, a, b0, b1)                                                 \
    asm volatile("mma.sync.aligned.m16n8k16.row.col.f32.f16.f16.f32 "          \
        "{%0,%1,%2,%3},{%4,%5,%6,%7},{%8,%9},{%0,%1,%2,%3};"                   \
        : "+f"((c)[0]), "+f"((c)[1]), "+f"((c)[2]), "+f"((c)[3])               \
        : "r"((a)[0]), "r"((a)[1]), "r"((a)[2]), "r"((a)[3]), "r"(b0), "r"(b1))

#define CPA16(dst, src, sz)                                                    \
    asm volatile("cp.async.cg.shared.global [%0], [%1], 16, %2;"               \
        :: "r"(dst), "l"(src), "r"(sz) : "memory")
#define CP_COMMIT() asm volatile("cp.async.commit_group;" ::: "memory")
#define CP_WAIT1()  asm volatile("cp.async.wait_group 1;" ::: "memory")
#define CP_WAIT0()  asm volatile("cp.async.wait_group 0;" ::: "memory")

__device__ __forceinline__ uint32_t pack_h2(__half a, __half b) {
    return (uint32_t)__half_as_ushort(a) | ((uint32_t)__half_as_ushort(b) << 16);
}

// ---------------------------------------------------------------------------
// prep_all: [0, 2048) ctrl conversion (4 y-rows per block); then weight packing
// ---------------------------------------------------------------------------
__global__ __launch_bounds__(256) void prep_all_kernel(
    const float* __restrict__ ctrl, const float* __restrict__ w1,
    const float* __restrict__ w2)
{
    __shared__ float sm[16 * 4 * 132];
    const int bid = blockIdx.x;
    const int tid = threadIdx.x;

    if (bid < 2048) {
        const int ys = bid & 31;
        const int bc = bid >> 5;
        const int chunk = bc & 7;
        const int b = bc >> 3;

        const float* src = ctrl + (((size_t)b * CC + chunk * 16) * NH + ys * 4) * NW;
#pragma unroll
        for (int it = 0; it < 8; it++) {
            int e = tid + it * 256;
            int r = e >> 5, xi = e & 31;
            int c = r >> 2, yl = r & 3;
            float4 v = *(const float4*)(src + (size_t)c * NH * NW + yl * NW + xi * 4);
            *(float4*)(sm + (c * 4 + yl) * 132 + xi * 4) = v;
        }
        __syncthreads();

#pragma unroll
        for (int it = 0; it < 4; it++) {
            int idx = tid + it * 256;
            int q = idx & 1, x = (idx >> 1) & 127, yl = idx >> 8;
            uint32_t u[4];
#pragma unroll
            for (int jp = 0; jp < 4; jp++) {
                int c0 = q * 8 + 2 * jp;
                __half o0 = __float2half(sm[(c0 * 4 + yl) * 132 + x]);
                __half o1 = __float2half(sm[((c0 + 1) * 4 + yl) * 132 + x]);
                u[jp] = pack_h2(o0, o1);
            }
            int y = ys * 4 + yl;
            float4* dst = ((float4*)g_ctrlp) +
                (((size_t)(bc * 128 + y) * 128 + x) * 2 + q);
            dst[0] = make_float4(__uint_as_float(u[0]), __uint_as_float(u[1]),
                                 __uint_as_float(u[2]), __uint_as_float(u[3]));
        }
    } else {
        int idx = (bid - 2048) * 256 + tid;
        if (idx < 8 * 9 * 64 * 16) {
            int jc = idx & 15;
            int oc = (idx >> 4) & 63;
            int r = idx >> 10;
            int tap = r % 9, chunk = r / 9;
            int dy = tap / 3, dx = tap % 3;
            float w = 0.f;
            if (oc < C1)
                w = w1[((oc * CC + chunk * 16 + jc) * 3 + dy) * 3 + dx];
            int q = (jc >> 3) ^ ((oc >> 2) & 1);
            g_w1p[((chunk * 9 + tap) * 64 + oc) * 16 + q * 8 + (jc & 7)] =
                __float2half(w);
        } else {
            int i2 = idx - 8 * 9 * 64 * 16;
            if (i2 < 4 * 9 * 32 * 16) {
                int jc = i2 & 15;
                int oc = (i2 >> 4) & 31;
                int r = i2 >> 9;
                int tap = r % 9, chunk = r / 9;
                int dy = tap / 3, dx = tap % 3;
                int cin = chunk * 16 + jc;
                float w = 0.f;
                if (oc < C2 && cin < C1)
                    w = w2[((oc * C1 + cin) * 3 + dy) * 3 + dx];
                int q = (jc >> 3) ^ ((oc >> 2) & 1);
                g_w2p[((chunk * 9 + tap) * 32 + oc) * 16 + q * 8 + (jc & 7)] =
                    __float2half(w);
            }
        }
    }
}

// ---------------------------------------------------------------------------
// conv1 mma: M=256, N=64 (oc 56-63 are zero tiles -> skipped).
// Warp map: wpx=(warp&3)*64, half=warp>>2. half 0: n-tiles 0..3 (oc 0-31),
// half 1: n-tiles 0..2 (oc 32-55). Each SMSP gets one of each -> balanced.
// ---------------------------------------------------------------------------
#define C1_A_BUF 16640
#define C1_OFF_B 33280
#define C1_B_BUF 18432
#define C1_OFF_P 70144
#define C1_SMEM 70912

__global__ void __launch_bounds__(256, 2) conv1_mma_kernel(
    const float* __restrict__ b1, const float* __restrict__ gamma,
    const float* __restrict__ beta, const float* __restrict__ mean,
    const float* __restrict__ var)
{
    extern __shared__ char smem[];
    float* smemT = (float*)smem;
    float* smP = (float*)(smem + C1_OFF_P);
    const uint32_t sb = smem_u32(smem);
    const int tid = threadIdx.x;
    const int lane = tid & 31;
    const int warp = tid >> 5;
    const int b = blockIdx.x >> 6;
    const int y0 = (blockIdx.x & 63) * 2;
    const int wpx = (warp & 3) * 64;
    const int half = warp >> 2;
    const int wn = half * 32;
    const int NT = half ? 3 : 4;   // skip all-zero oc>=56 tiles

    if (tid < 64) {
        float s = 0.f, bb = 0.f, b1v = 0.f;
        if (tid < C1) {
            s = gamma[tid] * rsqrtf(var[tid] + 1e-5f);
            bb = beta[tid] - mean[tid] * s;
            b1v = b1[tid];
        }
        smP[tid] = b1v; smP[64 + tid] = s; smP[128 + tid] = bb;
    }
    if (tid < 32) {
        int q = tid & 1, col = (tid >> 1) & 1, s = (tid >> 2) & 3, d = (tid >> 4) & 1;
        int ri = s * 130 + (col ? 129 : 0);
        *(float4*)(smem + d * C1_A_BUF + ri * 32 + q * 16) =
            make_float4(0.f, 0.f, 0.f, 0.f);
    }

    const int rA = (lane & 7) + ((lane >> 3) & 1) * 8;
    const int qA = lane >> 4;
    int riA[4];
#pragma unroll
    for (int mt = 0; mt < 4; mt++) {
        int px = wpx + mt * 16 + rA;
        riA[mt] = (px >> 7) * 130 + (px & 127);
    }
    const int ocB = (lane & 7) + ((lane >> 4) << 3);
    const int qB = (lane >> 3) & 1;
    const int ocRow = wn + ocB;
    const uint32_t bSwz =
        sb + C1_OFF_B + (uint32_t)ocRow * 32 + (uint32_t)((qB ^ (ocRow >> 2)) & 1) * 16;

    float C[4][4][4];
#pragma unroll
    for (int i = 0; i < 4; i++)
#pragma unroll
        for (int j = 0; j < 4; j++)
#pragma unroll
            for (int k = 0; k < 4; k++) C[i][j][k] = 0.f;

    const char* ctrlBase = (const char*)g_ctrlp;
    const char* wBase = (const char*)g_w1p;

    auto stage = [&](int c, int d) {
        const char* srcA = ctrlBase + (size_t)(b * 8 + c) * (128 * 128 * 32);
        uint32_t aB = sb + d * C1_A_BUF;
#pragma unroll
        for (int it = 0; it < 4; it++) {
            int e = tid + it * 256;
            int s = e >> 8, r5 = e & 255;
            int x = r5 >> 1, q = r5 & 1;
            int gy = y0 - 1 + s;
            int gyc = gy < 0 ? 0 : (gy > 127 ? 127 : gy);
            const char* src = srcA + ((size_t)gyc * 128 + x) * 32 + q * 16;
            int ri = s * 130 + x + 1;
            uint32_t dst = aB + ri * 32 + ((q ^ (ri >> 2)) & 1) * 16;
            CPA16(dst, src, ((unsigned)gy < 128u) ? 16 : 0);
        }
        uint32_t bBf = sb + C1_OFF_B + d * C1_B_BUF;
        const char* srcB = wBase + (size_t)c * C1_B_BUF;
        for (int e = tid; e < 1152; e += 256)
            CPA16(bBf + e * 16, srcB + e * 16, 16);
        CP_COMMIT();
    };

    stage(0, 0);
    for (int c = 0; c < 8; c++) {
        if (c < 7) { stage(c + 1, (c + 1) & 1); CP_WAIT1(); }
        else CP_WAIT0();
        __syncthreads();

        const uint32_t aBuf = sb + (c & 1) * C1_A_BUF;
        const uint32_t bBuf = bSwz + (c & 1) * C1_B_BUF;
#pragma unroll
        for (int dy = 0; dy < 3; dy++) {
#pragma unroll
            for (int dx = 0; dx < 3; dx++) {
                const int tap = dy * 3 + dx;
                uint32_t bh[8];
                uint32_t bt = bBuf + tap * 2048;
                LDSM4(bh, bt);
                LDSM4(bh + 4, bt + 512);
                uint32_t a[16];
#pragma unroll
                for (int mt = 0; mt < 4; mt++) {
                    int rt = riA[mt] + dy * 130 + dx;
                    uint32_t ad = aBuf + rt * 32 + ((qA ^ (rt >> 2)) & 1) * 16;
                    LDSM4(a + mt * 4, ad);
                }
#pragma unroll
                for (int mt = 0; mt < 4; mt++)
#pragma unroll
                    for (int nt = 0; nt < 4; nt++)
                        if (nt < NT)
                            MMA16816(C[mt][nt], a + mt * 4, bh[nt * 2], bh[nt * 2 + 1]);
            }
        }
        __syncthreads();
    }

    {
        const int g2 = lane >> 2, t4 = lane & 3;
#pragma unroll
        for (int mt = 0; mt < 4; mt++) {
#pragma unroll
            for (int nt = 0; nt < 4; nt++) {
                if (nt >= NT) continue;
                int px = wpx + mt * 16 + g2;
                int oc = wn + nt * 8 + t4 * 2;
                smemT[oc * 265 + px] = C[mt][nt][0];
                smemT[(oc + 1) * 265 + px] = C[mt][nt][1];
                smemT[oc * 265 + px + 8] = C[mt][nt][2];
                smemT[(oc + 1) * 265 + px + 8] = C[mt][nt][3];
            }
        }
    }
    __syncthreads();
    for (int e = tid; e < 1024; e += 256) {
        int c = e >> 8, px = e & 255;
        int gy = y0 + (px >> 7), x = px & 127;
        uint32_t uh[8];
#pragma unroll
        for (int jp = 0; jp < 8; jp++) {
            __half oh[2];
#pragma unroll
            for (int t = 0; t < 2; t++) {
                int oc = c * 16 + 2 * jp + t;
                float val = 0.f;
                if (oc < C1) {
                    float acc = smemT[oc * 265 + px];
                    val = fmaxf(acc + smP[oc], 0.f) * smP[64 + oc] + smP[128 + oc];
                }
                oh[t] = __float2half(val);
            }
            uh[jp] = pack_h2(oh[0], oh[1]);
        }
        float4* dst = ((float4*)g_hp) + (((size_t)(b * 4 + c) * 128 + gy) * 128 + x) * 2;
        dst[0] = make_float4(__uint_as_float(uh[0]), __uint_as_float(uh[1]),
                             __uint_as_float(uh[2]), __uint_as_float(uh[3]));
        dst[1] = make_float4(__uint_as_float(uh[4]), __uint_as_float(uh[5]),
                             __uint_as_float(uh[6]), __uint_as_float(uh[7]));
    }
}

// ---------------------------------------------------------------------------
// conv2 mma: M=512, N=32 but oc 24-31 are zero tiles -> compute n-tiles 0..2.
// ---------------------------------------------------------------------------
#define C2_A_BUF 24960
#define C2_OFF_B 49920
#define C2_B_BUF 9216
#define C2_SMEM 68352

__global__ void __launch_bounds__(256, 2) conv2_mma_kernel(const float* __restrict__ b2)
{
    extern __shared__ char smem[];
    float* smemT = (float*)smem;
    const uint32_t sb = smem_u32(smem);
    const int tid = threadIdx.x;
    const int lane = tid & 31;
    const int warp = tid >> 5;
    const int b = blockIdx.x >> 5;
    const int y0 = (blockIdx.x & 31) * 4;
    const int wpx = warp * 64;

    if (tid < 48) {
        int q = tid & 1, col = (tid >> 1) & 1, s = (tid >> 2) % 6, d = tid >= 24 ? 1 : 0;
        int ri = s * 130 + (col ? 129 : 0);
        *(float4*)(smem + d * C2_A_BUF + ri * 32 + q * 16) =
            make_float4(0.f, 0.f, 0.f, 0.f);
    }

    const int rA = (lane & 7) + ((lane >> 3) & 1) * 8;
    const int qA = lane >> 4;
    int riA[4];
#pragma unroll
    for (int mt = 0; mt < 4; mt++) {
        int px = wpx + mt * 16 + rA;
        riA[mt] = (px >> 7) * 130 + (px & 127);
    }
    const int ocB = (lane & 7) + ((lane >> 4) << 3);
    const int qB = (lane >> 3) & 1;
    const uint32_t bSwz =
        sb + C2_OFF_B + (uint32_t)ocB * 32 + (uint32_t)((qB ^ (ocB >> 2)) & 1) * 16;

    float C[4][3][4];
#pragma unroll
    for (int i = 0; i < 4; i++)
#pragma unroll
        for (int j = 0; j < 3; j++)
#pragma unroll
            for (int k = 0; k < 4; k++) C[i][j][k] = 0.f;

    const char* hpBase = (const char*)g_hp;
    const char* wBase = (const char*)g_w2p;

    auto stage = [&](int c, int d) {
        const char* srcA = hpBase + (size_t)(b * 4 + c) * (128 * 128 * 32);
        uint32_t aB = sb + d * C2_A_BUF;
#pragma unroll
        for (int it = 0; it < 6; it++) {
            int e = tid + it * 256;
            int s = e >> 8, r5 = e & 255;
            int x = r5 >> 1, q = r5 & 1;
            int gy = y0 - 1 + s;
            int gyc = gy < 0 ? 0 : (gy > 127 ? 127 : gy);
            const char* src = srcA + ((size_t)gyc * 128 + x) * 32 + q * 16;
            int ri = s * 130 + x + 1;
            uint32_t dst = aB + ri * 32 + ((q ^ (ri >> 2)) & 1) * 16;
            CPA16(dst, src, ((unsigned)gy < 128u) ? 16 : 0);
        }
        uint32_t bBf = sb + C2_OFF_B + d * C2_B_BUF;
        const char* srcB = wBase + (size_t)c * C2_B_BUF;
        for (int e = tid; e < 576; e += 256)
            CPA16(bBf + e * 16, srcB + e * 16, 16);
        CP_COMMIT();
    };

    stage(0, 0);
    for (int c = 0; c < 4; c++) {
        if (c < 3) { stage(c + 1, (c + 1) & 1); CP_WAIT1(); }
        else CP_WAIT0();
        __syncthreads();

        const uint32_t aBuf = sb + (c & 1) * C2_A_BUF;
        const uint32_t bBuf = bSwz + (c & 1) * C2_B_BUF;
#pragma unroll
        for (int dy = 0; dy < 3; dy++) {
#pragma unroll
            for (int dx = 0; dx < 3; dx++) {
                const int tap = dy * 3 + dx;
                uint32_t bh[8];
                uint32_t bt = bBuf + tap * 1024;
                LDSM4(bh, bt);
                LDSM4(bh + 4, bt + 512);
                uint32_t a[16];
#pragma unroll
                for (int mt = 0; mt < 4; mt++) {
                    int rt = riA[mt] + dy * 130 + dx;
                    uint32_t ad = aBuf + rt * 32 + ((qA ^ (rt >> 2)) & 1) * 16;
                    LDSM4(a + mt * 4, ad);
                }
#pragma unroll
                for (int mt = 0; mt < 4; mt++)
#pragma unroll
                    for (int nt = 0; nt < 3; nt++)
                        MMA16816(C[mt][nt], a + mt * 4, bh[nt * 2], bh[nt * 2 + 1]);
            }
        }
        __syncthreads();
    }

    {
        const int g2 = lane >> 2, t4 = lane & 3;
#pragma unroll
        for (int mt = 0; mt < 4; mt++) {
#pragma unroll
            for (int nt = 0; nt < 3; nt++) {
                int px = wpx + mt * 16 + g2;
                int oc = nt * 8 + t4 * 2;
                smemT[oc * 516 + px] = C[mt][nt][0];
                smemT[(oc + 1) * 516 + px] = C[mt][nt][1];
                smemT[oc * 516 + px + 8] = C[mt][nt][2];
                smemT[(oc + 1) * 516 + px + 8] = C[mt][nt][3];
            }
        }
    }
    __syncthreads();
    for (int e = tid; e < C2 * 128; e += 256) {
        int oc = e >> 7, pq = e & 127;
        int px0 = pq * 4;
        int gy = y0 + (px0 >> 7), x = px0 & 127;
        float bv = b2[oc];
        float4 v = *(float4*)(smemT + oc * 516 + px0);
        v.x += bv; v.y += bv; v.z += bv; v.w += bv;
        *(float4*)(g_cond + (((size_t)b * C2 + oc) * NH + gy) * NW + x) = v;
    }
}

// ---------------------------------------------------------------------------
// translate — best-known version (1 cell/thread)
// ---------------------------------------------------------------------------
__global__ __launch_bounds__(256) void translate_kernel(
    const float* __restrict__ image, float* __restrict__ out)
{
    const int x4 = threadIdx.x;
    const int cellY = blockIdx.x * 2 + threadIdx.y;
    const int ch = blockIdx.y;
    const int b = blockIdx.z;
    const int g = ch / 3;

    float wk[9];
    const float* cond_b = g_cond + ((size_t)b * C2 + g * 9) * NH * NW;
#pragma unroll
    for (int k = 0; k < 9; k++)
        wk[k] = cond_b[(size_t)k * NH * NW + (size_t)cellY * NW + x4];

    const float4* img4 = (const float4*)image + (size_t)(b * 6 + ch) * HH * (WW / 4);
    float4* out4 = (float4*)out + (size_t)(b * 6 + ch) * HH * (WW / 4);

#pragma unroll
    for (int r = 0; r < 4; r++) {
        int y = cellY * 4 + r;
        float4 acc = make_float4(0.f, 0.f, 0.f, 0.f);
#pragma unroll
        for (int i = 0; i < 3; i++) {
            int xf = x4 + i - 1;
            if ((unsigned)xf >= (unsigned)(WW / 4)) continue;
#pragma unroll
            for (int j = 0; j < 3; j++) {
                int yy = y + j * 4 - 4;
                if ((unsigned)yy >= (unsigned)HH) continue;
                float w = wk[i * 3 + j];
                float4 v = img4[(size_t)yy * (WW / 4) + xf];
                acc.x += v.x * w; acc.y += v.y * w;
                acc.z += v.z * w; acc.w += v.w * w;
            }
        }
        out4[(size_t)y * (WW / 4) + x4] = acc;
    }
}

// ---------------------------------------------------------------------------
extern "C" void kernel_launch(void* const* d_in, const int* in_sizes, int n_in,
                              void* d_out, int out_size)
{
    const float* image = (const float*)d_in[0];
    const float* ctrl  = (const float*)d_in[1];
    const float* w1    = (const float*)d_in[2];
    const float* b1    = (const float*)d_in[3];
    const float* gamma = (const float*)d_in[4];
    const float* beta  = (const float*)d_in[5];
    const float* mean  = (const float*)d_in[6];
    const float* var   = (const float*)d_in[7];
    const float* w2    = (const float*)d_in[8];
    const float* b2    = (const float*)d_in[9];
    float* out = (float*)d_out;

    static int smem_set = 0;
    if (!smem_set) {
        cudaFuncSetAttribute(conv1_mma_kernel,
                             cudaFuncAttributeMaxDynamicSharedMemorySize, C1_SMEM);
        cudaFuncSetAttribute(conv2_mma_kernel,
                             cudaFuncAttributeMaxDynamicSharedMemorySize, C2_SMEM);
        smem_set = 1;
    }

    prep_all_kernel<<<2048 + 360, 256>>>(ctrl, w1, w2);
    conv1_mma_kernel<<<BB * 64, 256, C1_SMEM>>>(b1, gamma, beta, mean, var);
    conv2_mma_kernel<<<BB * 32, 256, C2_SMEM>>>(b2);
    translate_kernel<<<dim3(64, 6, BB), dim3(128, 2)>>>(image, out);
}

// round 14
// speedup vs baseline: 1.0668x; 1.0368x over previous
#include <cuda_runtime.h>
#include <cuda_fp16.h>
#include <cstdint>

#define BB 8
#define CC 128
#define NH 128
#define NW 128
#define C1 50
#define C2 18
#define HH 512
#define WW 512

// ---------------------------------------------------------------------------
// Device-global scratch
// ---------------------------------------------------------------------------
__device__ __align__(16) __half g_ctrlp[(size_t)BB * 8 * NH * NW * 16];
__device__ __align__(16) __half g_hp[(size_t)BB * 4 * NH * NW * 16];
__device__ float g_cond[(size_t)BB * C2 * NH * NW];
__device__ __align__(16) __half g_w1p[8 * 9 * 64 * 16];
__device__ __align__(16) __half g_w2p[4 * 9 * 32 * 16];

__device__ __forceinline__ uint32_t smem_u32(const void* p) {
    uint32_t a;
    asm("{ .reg .u64 t; cvta.to.shared.u64 t, %1; cvt.u32.u64 %0, t; }"
        : "=r"(a) : "l"(p));
    return a;
}

#define LDSM4(r, a)                                                            \
    asm volatile("ldmatrix.sync.aligned.m8n8.x4.shared.b16 {%0,%1,%2,%3}, [%4];" \
        : "=r"((r)[0]), "=r"((r)[1]), "=r"((r)[2]), "=r"((r)[3]) : "r"(a))

#define MMA16816(c, a, b0, b1)                                                 \
    asm volatile("mma.sync.aligned.m16n8k16.row.col.f32.f16.f16.f32 "          \
        "{%0,%1,%2,%3},{%4,%5,%6,%7},{%8,%9},{%0,%1,%2,%3};"                   \
        : "+f"((c)[0]), "+f"((c)[1]), "+f"((c)[2]), "+f"((c)[3])               \
        : "r"((a)[0]), "r"((a)[1]), "r"((a)[2]), "r"((a)[3]), "r"(b0), "r"(b1))

#define CPA16(dst, src, sz)                                                    \
    asm volatile("cp.async.cg.shared.global [%0], [%1], 16, %2;"               \
        :: "r"(dst), "l"(src), "r"(sz) : "memory")
#define CP_COMMIT() asm volatile("cp.async.commit_group;" ::: "memory")
#define CP_WAIT1()  asm volatile("cp.async.wait_group 1;" ::: "memory")
#define CP_WAIT0()  asm volatile("cp.async.wait_group 0;" ::: "memory")

__device__ __forceinline__ uint32_t pack_h2(__half a, __half b) {
    return (uint32_t)__half_as_ushort(a) | ((uint32_t)__half_as_ushort(b) << 16);
}

// ---------------------------------------------------------------------------
// prep_all: [0, 2048) ctrl conversion (direct, no smem); then weight packing
// block = (b, chunk, ys): converts 16 cins x 4 rows x 128 px
// thread (x, q, yl): reads 8 coalesced scalars, writes one float4
// ---------------------------------------------------------------------------
__global__ __launch_bounds__(256) void prep_all_kernel(
    const float* __restrict__ ctrl, const float* __restrict__ w1,
    const float* __restrict__ w2)
{
    const int bid = blockIdx.x;
    const int tid = threadIdx.x;

    if (bid < 2048) {
        const int ys = bid & 31;
        const int bc = bid >> 5;
        const int chunk = bc & 7;
        const int b = bc >> 3;

        const float* src = ctrl + (((size_t)b * CC + chunk * 16) * NH + ys * 4) * NW;
#pragma unroll
        for (int it = 0; it < 4; it++) {
            int idx = tid + it * 256;
            int q = idx & 1, x = (idx >> 1) & 127, yl = idx >> 8;
            const float* s = src + (size_t)(q * 8) * NH * NW + yl * NW + x;
            uint32_t u[4];
#pragma unroll
            for (int jp = 0; jp < 4; jp++) {
                __half o0 = __float2half(s[(size_t)(2 * jp) * NH * NW]);
                __half o1 = __float2half(s[(size_t)(2 * jp + 1) * NH * NW]);
                u[jp] = pack_h2(o0, o1);
            }
            int y = ys * 4 + yl;
            float4* dst = ((float4*)g_ctrlp) +
                (((size_t)(bc * 128 + y) * 128 + x) * 2 + q);
            dst[0] = make_float4(__uint_as_float(u[0]), __uint_as_float(u[1]),
                                 __uint_as_float(u[2]), __uint_as_float(u[3]));
        }
    } else {
        int idx = (bid - 2048) * 256 + tid;
        if (idx < 8 * 9 * 64 * 16) {
            int jc = idx & 15;
            int oc = (idx >> 4) & 63;
            int r = idx >> 10;
            int tap = r % 9, chunk = r / 9;
            int dy = tap / 3, dx = tap % 3;
            float w = 0.f;
            if (oc < C1)
                w = w1[((oc * CC + chunk * 16 + jc) * 3 + dy) * 3 + dx];
            int q = (jc >> 3) ^ ((oc >> 2) & 1);
            g_w1p[((chunk * 9 + tap) * 64 + oc) * 16 + q * 8 + (jc & 7)] =
                __float2half(w);
        } else {
            int i2 = idx - 8 * 9 * 64 * 16;
            if (i2 < 4 * 9 * 32 * 16) {
                int jc = i2 & 15;
                int oc = (i2 >> 4) & 31;
                int r = i2 >> 9;
                int tap = r % 9, chunk = r / 9;
                int dy = tap / 3, dx = tap % 3;
                int cin = chunk * 16 + jc;
                float w = 0.f;
                if (oc < C2 && cin < C1)
                    w = w2[((oc * C1 + cin) * 3 + dy) * 3 + dx];
                int q = (jc >> 3) ^ ((oc >> 2) & 1);
                g_w2p[((chunk * 9 + tap) * 32 + oc) * 16 + q * 8 + (jc & 7)] =
                    __float2half(w);
            }
        }
    }
}

// ---------------------------------------------------------------------------
// conv1 mma: M=256, N=64 (oc 56-63 zero tiles skipped).
// Warp map: wpx=(warp&3)*64, half=warp>>2; half 0: n-tiles 0..3, half 1: 0..2.
// ---------------------------------------------------------------------------
#define C1_A_BUF 16640
#define C1_OFF_B 33280
#define C1_B_BUF 18432
#define C1_OFF_P 70144
#define C1_SMEM 70912

__global__ void __launch_bounds__(256, 2) conv1_mma_kernel(
    const float* __restrict__ b1, const float* __restrict__ gamma,
    const float* __restrict__ beta, const float* __restrict__ mean,
    const float* __restrict__ var)
{
    extern __shared__ char smem[];
    float* smemT = (float*)smem;
    float* smP = (float*)(smem + C1_OFF_P);
    const uint32_t sb = smem_u32(smem);
    const int tid = threadIdx.x;
    const int lane = tid & 31;
    const int warp = tid >> 5;
    const int b = blockIdx.x >> 6;
    const int y0 = (blockIdx.x & 63) * 2;
    const int wpx = (warp & 3) * 64;
    const int half = warp >> 2;
    const int wn = half * 32;
    const int NT = half ? 3 : 4;

    if (tid < 64) {
        float s = 0.f, bb = 0.f, b1v = 0.f;
        if (tid < C1) {
            s = gamma[tid] * rsqrtf(var[tid] + 1e-5f);
            bb = beta[tid] - mean[tid] * s;
            b1v = b1[tid];
        }
        smP[tid] = b1v; smP[64 + tid] = s; smP[128 + tid] = bb;
    }
    if (tid < 32) {
        int q = tid & 1, col = (tid >> 1) & 1, s = (tid >> 2) & 3, d = (tid >> 4) & 1;
        int ri = s * 130 + (col ? 129 : 0);
        *(float4*)(smem + d * C1_A_BUF + ri * 32 + q * 16) =
            make_float4(0.f, 0.f, 0.f, 0.f);
    }

    const int rA = (lane & 7) + ((lane >> 3) & 1) * 8;
    const int qA = lane >> 4;
    int riA[4];
#pragma unroll
    for (int mt = 0; mt < 4; mt++) {
        int px = wpx + mt * 16 + rA;
        riA[mt] = (px >> 7) * 130 + (px & 127);
    }
    const int ocB = (lane & 7) + ((lane >> 4) << 3);
    const int qB = (lane >> 3) & 1;
    const int ocRow = wn + ocB;
    const uint32_t bSwz =
        sb + C1_OFF_B + (uint32_t)ocRow * 32 + (uint32_t)((qB ^ (ocRow >> 2)) & 1) * 16;

    float C[4][4][4];
#pragma unroll
    for (int i = 0; i < 4; i++)
#pragma unroll
        for (int j = 0; j < 4; j++)
#pragma unroll
            for (int k = 0; k < 4; k++) C[i][j][k] = 0.f;

    const char* ctrlBase = (const char*)g_ctrlp;
    const char* wBase = (const char*)g_w1p;

    auto stage = [&](int c, int d) {
        const char* srcA = ctrlBase + (size_t)(b * 8 + c) * (128 * 128 * 32);
        uint32_t aB = sb + d * C1_A_BUF;
#pragma unroll
        for (int it = 0; it < 4; it++) {
            int e = tid + it * 256;
            int s = e >> 8, r5 = e & 255;
            int x = r5 >> 1, q = r5 & 1;
            int gy = y0 - 1 + s;
            int gyc = gy < 0 ? 0 : (gy > 127 ? 127 : gy);
            const char* src = srcA + ((size_t)gyc * 128 + x) * 32 + q * 16;
            int ri = s * 130 + x + 1;
            uint32_t dst = aB + ri * 32 + ((q ^ (ri >> 2)) & 1) * 16;
            CPA16(dst, src, ((unsigned)gy < 128u) ? 16 : 0);
        }
        uint32_t bBf = sb + C1_OFF_B + d * C1_B_BUF;
        const char* srcB = wBase + (size_t)c * C1_B_BUF;
        for (int e = tid; e < 1152; e += 256)
            CPA16(bBf + e * 16, srcB + e * 16, 16);
        CP_COMMIT();
    };

    stage(0, 0);
    for (int c = 0; c < 8; c++) {
        if (c < 7) { stage(c + 1, (c + 1) & 1); CP_WAIT1(); }
        else CP_WAIT0();
        __syncthreads();

        const uint32_t aBuf = sb + (c & 1) * C1_A_BUF;
        const uint32_t bBuf = bSwz + (c & 1) * C1_B_BUF;
#pragma unroll
        for (int dy = 0; dy < 3; dy++) {
#pragma unroll
            for (int dx = 0; dx < 3; dx++) {
                const int tap = dy * 3 + dx;
                uint32_t bh[8];
                uint32_t bt = bBuf + tap * 2048;
                LDSM4(bh, bt);
                LDSM4(bh + 4, bt + 512);
                uint32_t a[16];
#pragma unroll
                for (int mt = 0; mt < 4; mt++) {
                    int rt = riA[mt] + dy * 130 + dx;
                    uint32_t ad = aBuf + rt * 32 + ((qA ^ (rt >> 2)) & 1) * 16;
                    LDSM4(a + mt * 4, ad);
                }
#pragma unroll
                for (int mt = 0; mt < 4; mt++)
#pragma unroll
                    for (int nt = 0; nt < 4; nt++)
                        if (nt < NT)
                            MMA16816(C[mt][nt], a + mt * 4, bh[nt * 2], bh[nt * 2 + 1]);
            }
        }
        __syncthreads();
    }

    {
        const int g2 = lane >> 2, t4 = lane & 3;
#pragma unroll
        for (int mt = 0; mt < 4; mt++) {
#pragma unroll
            for (int nt = 0; nt < 4; nt++) {
                if (nt >= NT) continue;
                int px = wpx + mt * 16 + g2;
                int oc = wn + nt * 8 + t4 * 2;
                smemT[oc * 265 + px] = C[mt][nt][0];
                smemT[(oc + 1) * 265 + px] = C[mt][nt][1];
                smemT[oc * 265 + px + 8] = C[mt][nt][2];
                smemT[(oc + 1) * 265 + px + 8] = C[mt][nt][3];
            }
        }
    }
    __syncthreads();
    for (int e = tid; e < 1024; e += 256) {
        int c = e >> 8, px = e & 255;
        int gy = y0 + (px >> 7), x = px & 127;
        uint32_t uh[8];
#pragma unroll
        for (int jp = 0; jp < 8; jp++) {
            __half oh[2];
#pragma unroll
            for (int t = 0; t < 2; t++) {
                int oc = c * 16 + 2 * jp + t;
                float val = 0.f;
                if (oc < C1) {
                    float acc = smemT[oc * 265 + px];
                    val = fmaxf(acc + smP[oc], 0.f) * smP[64 + oc] + smP[128 + oc];
                }
                oh[t] = __float2half(val);
            }
            uh[jp] = pack_h2(oh[0], oh[1]);
        }
        float4* dst = ((float4*)g_hp) + (((size_t)(b * 4 + c) * 128 + gy) * 128 + x) * 2;
        dst[0] = make_float4(__uint_as_float(uh[0]), __uint_as_float(uh[1]),
                             __uint_as_float(uh[2]), __uint_as_float(uh[3]));
        dst[1] = make_float4(__uint_as_float(uh[4]), __uint_as_float(uh[5]),
                             __uint_as_float(uh[6]), __uint_as_float(uh[7]));
    }
}

// ---------------------------------------------------------------------------
// conv2 mma: M=512, N=32 with n-tiles 0..2 (oc 24-31 zero tiles skipped).
// ---------------------------------------------------------------------------
#define C2_A_BUF 24960
#define C2_OFF_B 49920
#define C2_B_BUF 9216
#define C2_SMEM 68352

__global__ void __launch_bounds__(256, 2) conv2_mma_kernel(const float* __restrict__ b2)
{
    extern __shared__ char smem[];
    float* smemT = (float*)smem;
    const uint32_t sb = smem_u32(smem);
    const int tid = threadIdx.x;
    const int lane = tid & 31;
    const int warp = tid >> 5;
    const int b = blockIdx.x >> 5;
    const int y0 = (blockIdx.x & 31) * 4;
    const int wpx = warp * 64;

    if (tid < 48) {
        int q = tid & 1, col = (tid >> 1) & 1, s = (tid >> 2) % 6, d = tid >= 24 ? 1 : 0;
        int ri = s * 130 + (col ? 129 : 0);
        *(float4*)(smem + d * C2_A_BUF + ri * 32 + q * 16) =
            make_float4(0.f, 0.f, 0.f, 0.f);
    }

    const int rA = (lane & 7) + ((lane >> 3) & 1) * 8;
    const int qA = lane >> 4;
    int riA[4];
#pragma unroll
    for (int mt = 0; mt < 4; mt++) {
        int px = wpx + mt * 16 + rA;
        riA[mt] = (px >> 7) * 130 + (px & 127);
    }
    const int ocB = (lane & 7) + ((lane >> 4) << 3);
    const int qB = (lane >> 3) & 1;
    const uint32_t bSwz =
        sb + C2_OFF_B + (uint32_t)ocB * 32 + (uint32_t)((qB ^ (ocB >> 2)) & 1) * 16;

    float C[4][3][4];
#pragma unroll
    for (int i = 0; i < 4; i++)
#pragma unroll
        for (int j = 0; j < 3; j++)
#pragma unroll
            for (int k = 0; k < 4; k++) C[i][j][k] = 0.f;

    const char* hpBase = (const char*)g_hp;
    const char* wBase = (const char*)g_w2p;

    auto stage = [&](int c, int d) {
        const char* srcA = hpBase + (size_t)(b * 4 + c) * (128 * 128 * 32);
        uint32_t aB = sb + d * C2_A_BUF;
#pragma unroll
        for (int it = 0; it < 6; it++) {
            int e = tid + it * 256;
            int s = e >> 8, r5 = e & 255;
            int x = r5 >> 1, q = r5 & 1;
            int gy = y0 - 1 + s;
            int gyc = gy < 0 ? 0 : (gy > 127 ? 127 : gy);
            const char* src = srcA + ((size_t)gyc * 128 + x) * 32 + q * 16;
            int ri = s * 130 + x + 1;
            uint32_t dst = aB + ri * 32 + ((q ^ (ri >> 2)) & 1) * 16;
            CPA16(dst, src, ((unsigned)gy < 128u) ? 16 : 0);
        }
        uint32_t bBf = sb + C2_OFF_B + d * C2_B_BUF;
        const char* srcB = wBase + (size_t)c * C2_B_BUF;
        for (int e = tid; e < 576; e += 256)
            CPA16(bBf + e * 16, srcB + e * 16, 16);
        CP_COMMIT();
    };

    stage(0, 0);
    for (int c = 0; c < 4; c++) {
        if (c < 3) { stage(c + 1, (c + 1) & 1); CP_WAIT1(); }
        else CP_WAIT0();
        __syncthreads();

        const uint32_t aBuf = sb + (c & 1) * C2_A_BUF;
        const uint32_t bBuf = bSwz + (c & 1) * C2_B_BUF;
#pragma unroll
        for (int dy = 0; dy < 3; dy++) {
#pragma unroll
            for (int dx = 0; dx < 3; dx++) {
                const int tap = dy * 3 + dx;
                uint32_t bh[8];
                uint32_t bt = bBuf + tap * 1024;
                LDSM4(bh, bt);
                LDSM4(bh + 4, bt + 512);
                uint32_t a[16];
#pragma unroll
                for (int mt = 0; mt < 4; mt++) {
                    int rt = riA[mt] + dy * 130 + dx;
                    uint32_t ad = aBuf + rt * 32 + ((qA ^ (rt >> 2)) & 1) * 16;
                    LDSM4(a + mt * 4, ad);
                }
#pragma unroll
                for (int mt = 0; mt < 4; mt++)
#pragma unroll
                    for (int nt = 0; nt < 3; nt++)
                        MMA16816(C[mt][nt], a + mt * 4, bh[nt * 2], bh[nt * 2 + 1]);
            }
        }
        __syncthreads();
    }

    {
        const int g2 = lane >> 2, t4 = lane & 3;
#pragma unroll
        for (int mt = 0; mt < 4; mt++) {
#pragma unroll
            for (int nt = 0; nt < 3; nt++) {
                int px = wpx + mt * 16 + g2;
                int oc = nt * 8 + t4 * 2;
                smemT[oc * 516 + px] = C[mt][nt][0];
                smemT[(oc + 1) * 516 + px] = C[mt][nt][1];
                smemT[oc * 516 + px + 8] = C[mt][nt][2];
                smemT[(oc + 1) * 516 + px + 8] = C[mt][nt][3];
            }
        }
    }
    __syncthreads();
    for (int e = tid; e < C2 * 128; e += 256) {
        int oc = e >> 7, pq = e & 127;
        int px0 = pq * 4;
        int gy = y0 + (px0 >> 7), x = px0 & 127;
        float bv = b2[oc];
        float4 v = *(float4*)(smemT + oc * 516 + px0);
        v.x += bv; v.y += bv; v.z += bv; v.w += bv;
        *(float4*)(g_cond + (((size_t)b * C2 + oc) * NH + gy) * NW + x) = v;
    }
}

// ---------------------------------------------------------------------------
// translate — best-known version (1 cell/thread)
// ---------------------------------------------------------------------------
__global__ __launch_bounds__(256) void translate_kernel(
    const float* __restrict__ image, float* __restrict__ out)
{
    const int x4 = threadIdx.x;
    const int cellY = blockIdx.x * 2 + threadIdx.y;
    const int ch = blockIdx.y;
    const int b = blockIdx.z;
    const int g = ch / 3;

    float wk[9];
    const float* cond_b = g_cond + ((size_t)b * C2 + g * 9) * NH * NW;
#pragma unroll
    for (int k = 0; k < 9; k++)
        wk[k] = cond_b[(size_t)k * NH * NW + (size_t)cellY * NW + x4];

    const float4* img4 = (const float4*)image + (size_t)(b * 6 + ch) * HH * (WW / 4);
    float4* out4 = (float4*)out + (size_t)(b * 6 + ch) * HH * (WW / 4);

#pragma unroll
    for (int r = 0; r < 4; r++) {
        int y = cellY * 4 + r;
        float4 acc = make_float4(0.f, 0.f, 0.f, 0.f);
#pragma unroll
        for (int i = 0; i < 3; i++) {
            int xf = x4 + i - 1;
            if ((unsigned)xf >= (unsigned)(WW / 4)) continue;
#pragma unroll
            for (int j = 0; j < 3; j++) {
                int yy = y + j * 4 - 4;
                if ((unsigned)yy >= (unsigned)HH) continue;
                float w = wk[i * 3 + j];
                float4 v = img4[(size_t)yy * (WW / 4) + xf];
                acc.x += v.x * w; acc.y += v.y * w;
                acc.z += v.z * w; acc.w += v.w * w;
            }
        }
        out4[(size_t)y * (WW / 4) + x4] = acc;
    }
}

// ---------------------------------------------------------------------------
extern "C" void kernel_launch(void* const* d_in, const int* in_sizes, int n_in,
                              void* d_out, int out_size)
{
    const float* image = (const float*)d_in[0];
    const float* ctrl  = (const float*)d_in[1];
    const float* w1    = (const float*)d_in[2];
    const float* b1    = (const float*)d_in[3];
    const float* gamma = (const float*)d_in[4];
    const float* beta  = (const float*)d_in[5];
    const float* mean  = (const float*)d_in[6];
    const float* var   = (const float*)d_in[7];
    const float* w2    = (const float*)d_in[8];
    const float* b2    = (const float*)d_in[9];
    float* out = (float*)d_out;

    static int smem_set = 0;
    if (!smem_set) {
        cudaFuncSetAttribute(conv1_mma_kernel,
                             cudaFuncAttributeMaxDynamicSharedMemorySize, C1_SMEM);
        cudaFuncSetAttribute(conv2_mma_kernel,
                             cudaFuncAttributeMaxDynamicSharedMemorySize, C2_SMEM);
        smem_set = 1;
    }

    prep_all_kernel<<<2048 + 360, 256>>>(ctrl, w1, w2);
    conv1_mma_kernel<<<BB * 64, 256, C1_SMEM>>>(b1, gamma, beta, mean, var);
    conv2_mma_kernel<<<BB * 32, 256, C2_SMEM>>>(b2);
    translate_kernel<<<dim3(64, 6, BB), dim3(128, 2)>>>(image, out);
}